// round 1
// baseline (speedup 1.0000x reference)
#include <cuda_runtime.h>

// Problem constants
#define BB   32
#define CI_  128
#define CO_  128
#define HH   56
#define WW   56
#define CIK  (CI_ * 9)      // 1152
#define TH   8
#define TW   8
#define CIC  8
#define NCHUNK (CI_ / CIC)  // 16

// Scratch: per-sample weights, transposed to [b][ci][k][co] so the conv's
// per-chunk weight load is a contiguous copy.
__device__ float g_Wt[(size_t)BB * CI_ * 9 * CO_];   // 18.9 MB

// ---------------------------------------------------------------------------
// prep: Wt[b][ci][k][co] = eps[b][co][ci][k] * exp(psi[co][ci][k]) + mu[co][ci][k]
// 32x32 smem tile transpose: coalesced reads (along ci*k) and writes (along co).
// grid (1152/32=36, 128/32=4, 32), block (32, 8)
// ---------------------------------------------------------------------------
__global__ void prep_kernel(const float* __restrict__ eps,
                            const float* __restrict__ psi,
                            const float* __restrict__ mu) {
    __shared__ float t[32][33];
    int b    = blockIdx.z;
    int cik0 = blockIdx.x * 32;   // column tile within [0, 1152)
    int co0  = blockIdx.y * 32;   // row tile within [0, 128)
    int tx   = threadIdx.x;       // 0..31
    int ty   = threadIdx.y;       // 0..7

    const float* epsb = eps + (size_t)b * CO_ * CIK;
#pragma unroll
    for (int j = 0; j < 32; j += 8) {
        int co  = co0 + ty + j;
        int cik = cik0 + tx;
        float e = epsb[(size_t)co * CIK + cik];
        float p = psi[(size_t)co * CIK + cik];
        float m = mu [(size_t)co * CIK + cik];
        t[ty + j][tx] = fmaf(e, __expf(p), m);
    }
    __syncthreads();
    float* wb = g_Wt + (size_t)b * CIK * CO_;
#pragma unroll
    for (int j = 0; j < 32; j += 8) {
        int cik = cik0 + ty + j;
        int co  = co0 + tx;
        wb[(size_t)cik * CO_ + co] = t[tx][ty + j];
    }
}

// ---------------------------------------------------------------------------
// conv: one block = one (b, 8x8 spatial tile), all 128 co.
// 256 threads: tid>>4 -> co group (8 co each), tid&15 -> (row, x-half).
// Per thread: 8 co x 4 x = 32 accumulators.
// ci processed in chunks of 8; weights for a chunk are a contiguous 36.8 KB
// slice of g_Wt (float4 copy); input halo 8x10x10 with zero padding.
// grid (49, 32), block 256
// ---------------------------------------------------------------------------
__global__ __launch_bounds__(256, 2)
void conv_kernel(const float* __restrict__ in, float* __restrict__ out) {
    __shared__ __align__(16) float s_in[CIC][TH + 2][12];   // 3.84 KB (pad 10->12)
    __shared__ __align__(16) float s_w[CIC * 9][CO_];       // 36.9 KB

    int tile = blockIdx.x;           // 0..48
    int b    = blockIdx.y;           // 0..31
    int ty0  = (tile / 7) * TH;
    int tx0  = (tile % 7) * TW;

    int tid     = threadIdx.x;
    int cog     = tid >> 4;          // 16 co groups
    int co_base = cog * 8;
    int spg     = tid & 15;
    int r       = spg >> 1;          // output row within tile, 0..7
    int x4      = (spg & 1) * 4;     // output col start within tile, 0 or 4

    const float* inb = in   + (size_t)b * CI_ * (HH * WW);
    const float* wb  = g_Wt + (size_t)b * CIK * CO_;

    float acc[8][4];
#pragma unroll
    for (int c = 0; c < 8; c++)
#pragma unroll
        for (int j = 0; j < 4; j++) acc[c][j] = 0.f;

    for (int chunk = 0; chunk < NCHUNK; chunk++) {
        int ci_base = chunk * CIC;

        // weights: contiguous copy, 2304 float4 by 256 threads = 9 each
        {
            const float4* src = (const float4*)(wb + (size_t)ci_base * 9 * CO_);
            float4*       dst = (float4*)s_w;
#pragma unroll
            for (int i = 0; i < 9; i++)
                dst[tid + i * 256] = src[tid + i * 256];
        }
        // input halo: 8 ci x 10 x 10, zero-padded at image borders
        for (int i = tid; i < CIC * 100; i += 256) {
            int ci  = i / 100;
            int rem = i - ci * 100;
            int yy  = rem / 10;
            int xx  = rem - yy * 10;
            int gy  = ty0 + yy - 1;
            int gx  = tx0 + xx - 1;
            float v = 0.f;
            if (gy >= 0 && gy < HH && gx >= 0 && gx < WW)
                v = inb[(size_t)(ci_base + ci) * (HH * WW) + gy * WW + gx];
            s_in[ci][yy][xx] = v;
        }
        __syncthreads();

#pragma unroll 2
        for (int ci = 0; ci < CIC; ci++) {
#pragma unroll
            for (int kh = 0; kh < 3; kh++) {
                float4 a0 = *(const float4*)&s_in[ci][r + kh][x4];
                float4 a1 = *(const float4*)&s_in[ci][r + kh][x4 + 4];
                float in6[6] = {a0.x, a0.y, a0.z, a0.w, a1.x, a1.y};
#pragma unroll
                for (int kw = 0; kw < 3; kw++) {
                    const float* wrow = &s_w[(ci * 3 + kh) * 3 + kw][co_base];
                    float4 w0 = *(const float4*)&wrow[0];
                    float4 w1 = *(const float4*)&wrow[4];
                    float wv[8] = {w0.x, w0.y, w0.z, w0.w, w1.x, w1.y, w1.z, w1.w};
#pragma unroll
                    for (int c = 0; c < 8; c++)
#pragma unroll
                        for (int j = 0; j < 4; j++)
                            acc[c][j] = fmaf(wv[c], in6[kw + j], acc[c][j]);
                }
            }
        }
        __syncthreads();
    }

    // write: 8 STG.128 per thread, fully coalesced within a half-row
    float* ob = out + (size_t)b * CO_ * (HH * WW);
#pragma unroll
    for (int c = 0; c < 8; c++) {
        float4 v = make_float4(acc[c][0], acc[c][1], acc[c][2], acc[c][3]);
        *(float4*)&ob[(size_t)(co_base + c) * (HH * WW) + (ty0 + r) * WW + tx0 + x4] = v;
    }
}

extern "C" void kernel_launch(void* const* d_in, const int* in_sizes, int n_in,
                              void* d_out, int out_size) {
    const float* input = (const float*)d_in[0];   // [32,128,56,56]
    const float* eps   = (const float*)d_in[1];   // [32,128,128,3,3]
    const float* psi   = (const float*)d_in[2];   // [128,128,3,3]
    const float* mu    = (const float*)d_in[3];   // [128,128,3,3]
    float* out = (float*)d_out;                   // [32,128,56,56]

    dim3 pgrid(CIK / 32, CO_ / 32, BB);           // (36, 4, 32)
    dim3 pblk(32, 8);
    prep_kernel<<<pgrid, pblk>>>(eps, psi, mu);

    dim3 cgrid(49, BB);                           // 7x7 tiles x 32 batch
    conv_kernel<<<cgrid, 256>>>(input, out);
}

// round 4
// speedup vs baseline: 2.6042x; 2.6042x over previous
#include <cuda_runtime.h>
#include <cstdint>

// ---------------- problem constants ----------------
#define BB   32
#define CI_  128
#define CO_  128
#define HH   56
#define WW   56
#define HW   3136          // 56*56
#define CIK  (CI_ * 9)     // 1152
#define PADW 58            // padded spatial dim
#define MT   112           // CTA pixel tile (2 rows x 56)

// ---------------- scratch (device globals; no runtime alloc) ----------------
__device__ float g_Wt [(size_t)BB * CIK * CO_];            // [b][cik][co]
__device__ float g_W2 [(size_t)BB * 9 * CO_ * CI_];        // [b][tap][co][ci]
__device__ float g_pad[(size_t)BB * PADW * PADW * CI_];    // [b][y][x][ci]

// ---------------- helpers ----------------
__device__ __forceinline__ uint32_t smem_to_u32(const void* p) {
    uint32_t a;
    asm("{ .reg .u64 t; cvta.to.shared.u64 t, %1; cvt.u32.u64 %0, t; }" : "=r"(a) : "l"(p));
    return a;
}
__device__ __forceinline__ uint32_t f32_to_tf32(float f) {
    uint32_t r; asm("cvt.rna.tf32.f32 %0, %1;" : "=r"(r) : "f"(f)); return r;
}
__device__ __forceinline__ void ldsm_x4(uint32_t* r, uint32_t addr) {
    asm volatile("ldmatrix.sync.aligned.m8n8.x4.shared.b16 {%0,%1,%2,%3}, [%4];"
        : "=r"(r[0]), "=r"(r[1]), "=r"(r[2]), "=r"(r[3]) : "r"(addr));
}
__device__ __forceinline__ void mma_tf32(float* c, const uint32_t* a, const uint32_t* b) {
    asm volatile("mma.sync.aligned.m16n8k8.row.col.f32.tf32.tf32.f32 "
        "{%0,%1,%2,%3}, {%4,%5,%6,%7}, {%8,%9}, {%0,%1,%2,%3};"
        : "+f"(c[0]), "+f"(c[1]), "+f"(c[2]), "+f"(c[3])
        : "r"(a[0]), "r"(a[1]), "r"(a[2]), "r"(a[3]), "r"(b[0]), "r"(b[1]));
}

// ---------------------------------------------------------------------------
// prep 1: Wt[b][cik][co] = eps[b][co][cik] * exp(psi[co][cik]) + mu[co][cik]
// ---------------------------------------------------------------------------
__global__ void prep_kernel(const float* __restrict__ eps,
                            const float* __restrict__ psi,
                            const float* __restrict__ mu) {
    __shared__ float t[32][33];
    int b = blockIdx.z, cik0 = blockIdx.x * 32, co0 = blockIdx.y * 32;
    int tx = threadIdx.x, ty = threadIdx.y;
    const float* epsb = eps + (size_t)b * CO_ * CIK;
#pragma unroll
    for (int j = 0; j < 32; j += 8) {
        int co = co0 + ty + j, cik = cik0 + tx;
        float e = epsb[(size_t)co * CIK + cik];
        float p = psi[(size_t)co * CIK + cik];
        float m = mu [(size_t)co * CIK + cik];
        t[ty + j][tx] = fmaf(e, __expf(p), m);
    }
    __syncthreads();
    float* wb = g_Wt + (size_t)b * CIK * CO_;
#pragma unroll
    for (int j = 0; j < 32; j += 8)
        wb[(size_t)(cik0 + ty + j) * CO_ + co0 + tx] = t[tx][ty + j];
}

// ---------------------------------------------------------------------------
// prep 2: W2[b][tap][co][ci] = Wt[b][ci*9+tap][co]
// ---------------------------------------------------------------------------
__global__ void wtrans_kernel() {
    __shared__ float t[32][33];
    int b = blockIdx.z, k = blockIdx.y;
    int ci0 = (blockIdx.x >> 2) * 32, co0 = (blockIdx.x & 3) * 32;
    int tx = threadIdx.x, ty = threadIdx.y;
    const float* wb = g_Wt + (size_t)b * CIK * CO_;
#pragma unroll
    for (int j = 0; j < 32; j += 8)
        t[ty + j][tx] = wb[(size_t)((ci0 + ty + j) * 9 + k) * CO_ + co0 + tx];
    __syncthreads();
    float* o = g_W2 + ((size_t)(b * 9 + k) * CO_) * CI_;
#pragma unroll
    for (int j = 0; j < 32; j += 8)
        o[(size_t)(co0 + ty + j) * CI_ + ci0 + tx] = t[tx][ty + j];
}

// ---------------------------------------------------------------------------
// prep 3: zero the pad border of g_pad
// ---------------------------------------------------------------------------
__global__ void zeroborder_kernel() {
    int gi = blockIdx.x * 256 + threadIdx.x;
    if (gi >= BB * 228 * 32) return;
    int b = gi / (228 * 32);
    int r = gi % (228 * 32);
    int pi = r >> 5, f = r & 31;
    int y, x;
    if (pi < 58)       { y = 0;            x = pi; }
    else if (pi < 116) { y = 57;           x = pi - 58; }
    else if (pi < 172) { y = pi - 116 + 1; x = 0; }
    else               { y = pi - 172 + 1; x = 57; }
    ((float4*)g_pad)[(((size_t)b * PADW + y) * PADW + x) * 32 + f] = make_float4(0.f, 0.f, 0.f, 0.f);
}

// ---------------------------------------------------------------------------
// prep 4: NCHW -> padded NHWC
// ---------------------------------------------------------------------------
__global__ void intrans_kernel(const float* __restrict__ in) {
    __shared__ float t[32][33];
    int b = blockIdx.z, hw0 = blockIdx.x * 32, ci0 = blockIdx.y * 32;
    int tx = threadIdx.x, ty = threadIdx.y;
    const float* ib = in + (size_t)b * CI_ * HW;
#pragma unroll
    for (int j = 0; j < 32; j += 8)
        t[ty + j][tx] = ib[(size_t)(ci0 + ty + j) * HW + hw0 + tx];
    __syncthreads();
#pragma unroll
    for (int j = 0; j < 32; j += 8) {
        int hw = hw0 + ty + j;
        int y = hw / WW, x = hw - y * WW;
        g_pad[(((size_t)b * PADW + y + 1) * PADW + (x + 1)) * CI_ + ci0 + tx] = t[tx][ty + j];
    }
}

// ---------------------------------------------------------------------------
// conv: implicit GEMM with mma.sync tf32.
// CTA = 112 pixels (2 full rows) x 128 co; K streamed 9 taps x 4 ci-chunks(32).
// 8 warps: each computes all 112 M-rows x 16 co (7 m-frags x 2 n-frags).
// SMEM tiles in 128B rows with XOR-16B swizzle; frags via ldmatrix.x4.b16.
// grid (28, 32), block 256.
// ---------------------------------------------------------------------------
__global__ __launch_bounds__(256, 2) void conv_mma(float* __restrict__ out) {
    __shared__ __align__(128) uint32_t As[MT * 32];    // 112 rows x 32 tf32
    __shared__ __align__(128) uint32_t Bs[CO_ * 32];   // 128 rows x 32 tf32

    int tid = threadIdx.x, lid = tid & 31, wid = tid >> 5;
    int tile = blockIdx.x, b = blockIdx.y;
    int y0 = tile * 2;

    // ---- staging coordinates (per t4 slice) ----
    // A: 112 rows * 8 float4 = 896 elems; B: 128*8 = 1024
    const float* aBase[4];
    int  offA[4];
    bool avalid[4];
    const float* bBase[4];
    int  offB[4];
#pragma unroll
    for (int t4 = 0; t4 < 4; t4++) {
        int idx = tid + t4 * 256;
        // A
        avalid[t4] = (idx < MT * 8);
        int p = idx >> 3, j = idx & 7;
        int r1 = (p >= 56) ? 1 : 0;
        int px = p - 56 * r1;
        offA[t4] = p * 8 + (j ^ (p & 7));
        aBase[t4] = g_pad + (((size_t)b * PADW + (y0 + r1)) * PADW + px) * CI_ + j * 4;
        // B
        int co = idx >> 3, jb = idx & 7;
        offB[t4] = co * 8 + (jb ^ (co & 7));
        bBase[t4] = g_W2 + (size_t)b * 9 * CO_ * CI_ + (size_t)co * CI_ + jb * 4;
    }

    uint32_t As_addr = smem_to_u32(As);
    uint32_t Bs_addr = smem_to_u32(Bs);

    // ---- fragment lane addressing ----
    int rA   = lid & 7;                 // row within 8
    int add8A = ((lid >> 3) & 1) << 3;  // +8 rows for mats 1,3
    int jAh  = lid >> 4;                // +1 16B-block for mats 2,3
    uint32_t a_lane_base = As_addr + (uint32_t)(add8A + rA) * 128;
    int xorA = rA;                      // (row & 7) invariant under +8/+16

    int add8B = ((lid >> 4) & 1) << 3;  // lanes 16-31 -> rows +8 (nf1)
    int jBh  = (lid >> 3) & 1;          // lanes 8-15,24-31 -> +1 block
    uint32_t b_lane_base = Bs_addr + (uint32_t)(wid * 16 + add8B + rA) * 128;
    int xorB = rA;

    float acc[7][2][4];
#pragma unroll
    for (int mf = 0; mf < 7; mf++)
#pragma unroll
        for (int nf = 0; nf < 2; nf++)
#pragma unroll
            for (int q = 0; q < 4; q++) acc[mf][nf][q] = 0.f;

    for (int uv = 0; uv < 9; uv++) {
        int u = uv / 3, v = uv % 3;
        size_t ash = ((size_t)u * PADW + v) * CI_;     // tap shift in A
        size_t bsh = (size_t)uv * CO_ * CI_;           // tap shift in B
        for (int cc = 0; cc < 4; cc++) {
            int ccol = cc * 32;
            // ---- stage A ----
            uint4* AsV = (uint4*)As;
#pragma unroll
            for (int t4 = 0; t4 < 4; t4++) {
                if (avalid[t4]) {
                    float4 va = *(const float4*)(aBase[t4] + ash + ccol);
                    uint4 tv;
                    tv.x = f32_to_tf32(va.x); tv.y = f32_to_tf32(va.y);
                    tv.z = f32_to_tf32(va.z); tv.w = f32_to_tf32(va.w);
                    AsV[offA[t4]] = tv;
                }
            }
            // ---- stage B ----
            uint4* BsV = (uint4*)Bs;
#pragma unroll
            for (int t4 = 0; t4 < 4; t4++) {
                float4 wv = *(const float4*)(bBase[t4] + bsh + ccol);
                uint4 tw;
                tw.x = f32_to_tf32(wv.x); tw.y = f32_to_tf32(wv.y);
                tw.z = f32_to_tf32(wv.z); tw.w = f32_to_tf32(wv.w);
                BsV[offB[t4]] = tw;
            }
            __syncthreads();

            // ---- 4 k-steps of 8 ----
#pragma unroll
            for (int kk = 0; kk < 4; kk++) {
                uint32_t bf[4];
                ldsm_x4(bf, b_lane_base + (uint32_t)(((kk * 2 + jBh) ^ xorB) << 4));
#pragma unroll
                for (int mf = 0; mf < 7; mf++) {
                    uint32_t af[4];
                    ldsm_x4(af, a_lane_base + (uint32_t)(mf * 16) * 128
                                 + (uint32_t)(((kk * 2 + jAh) ^ xorA) << 4));
                    mma_tf32(acc[mf][0], af, bf);       // nf0: {bf0,bf1}
                    mma_tf32(acc[mf][1], af, bf + 2);   // nf1: {bf2,bf3}
                }
            }
            __syncthreads();
        }
    }

    // ---- epilogue: direct stores, NCHW ----
    float* ob = out + (size_t)b * CO_ * HW;
    int g = lid >> 2, tg = lid & 3;
#pragma unroll
    for (int mf = 0; mf < 7; mf++) {
#pragma unroll
        for (int h = 0; h < 2; h++) {
            int row = mf * 16 + g + 8 * h;
            int r1 = (row >= 56) ? 1 : 0;
            size_t pix = (size_t)(y0 + r1) * WW + (row - 56 * r1);
#pragma unroll
            for (int nf = 0; nf < 2; nf++) {
                int col = wid * 16 + nf * 8 + (tg << 1);
                ob[(size_t)col * HW + pix]       = acc[mf][nf][2 * h];
                ob[(size_t)(col + 1) * HW + pix] = acc[mf][nf][2 * h + 1];
            }
        }
    }
}

// ---------------------------------------------------------------------------
extern "C" void kernel_launch(void* const* d_in, const int* in_sizes, int n_in,
                              void* d_out, int out_size) {
    const float* input = (const float*)d_in[0];   // [32,128,56,56]
    const float* eps   = (const float*)d_in[1];   // [32,128,128,3,3]
    const float* psi   = (const float*)d_in[2];   // [128,128,3,3]
    const float* mu    = (const float*)d_in[3];   // [128,128,3,3]
    float* out = (float*)d_out;                   // [32,128,56,56]

    dim3 pblk(32, 8);
    prep_kernel<<<dim3(36, 4, BB), pblk>>>(eps, psi, mu);
    wtrans_kernel<<<dim3(16, 9, BB), pblk>>>();
    zeroborder_kernel<<<912, 256>>>();
    intrans_kernel<<<dim3(98, 4, BB), pblk>>>(input);

    conv_mma<<<dim3(28, BB), 256>>>(out);
}

// round 5
// speedup vs baseline: 3.8007x; 1.4595x over previous
#include <cuda_runtime.h>
#include <cstdint>

// ---------------- problem constants ----------------
#define BB   32
#define CI_  128
#define CO_  128
#define HH   56
#define WW   56
#define HW   3136          // 56*56
#define PADW 58            // padded spatial dim
#define MT   112           // CTA pixel tile (2 rows x 56)

#define AROWS 232          // 4 halo rows x 58 cols
#define ABYTES (AROWS * 128)        // 29696
#define BBYTES (CO_ * 128)          // 16384 per buffer
#define SMEM_CONV (ABYTES + 2 * BBYTES)   // 62464

// ---------------- scratch (device globals; no runtime alloc) ----------------
// both stored PRE-ROUNDED to tf32 bit patterns
__device__ float g_W2 [(size_t)BB * 9 * CO_ * CI_];        // [b][tap][co][ci]
__device__ float g_pad[(size_t)BB * PADW * PADW * CI_];    // [b][y][x][ci]

// ---------------- helpers ----------------
__device__ __forceinline__ uint32_t smem_to_u32(const void* p) {
    uint32_t a;
    asm("{ .reg .u64 t; cvta.to.shared.u64 t, %1; cvt.u32.u64 %0, t; }" : "=r"(a) : "l"(p));
    return a;
}
__device__ __forceinline__ uint32_t f32_to_tf32(float f) {
    uint32_t r; asm("cvt.rna.tf32.f32 %0, %1;" : "=r"(r) : "f"(f)); return r;
}
__device__ __forceinline__ void ldsm_x4(uint32_t* r, uint32_t addr) {
    asm volatile("ldmatrix.sync.aligned.m8n8.x4.shared.b16 {%0,%1,%2,%3}, [%4];"
        : "=r"(r[0]), "=r"(r[1]), "=r"(r[2]), "=r"(r[3]) : "r"(addr));
}
__device__ __forceinline__ void mma_tf32(float* c, const uint32_t* a, const uint32_t* b) {
    asm volatile("mma.sync.aligned.m16n8k8.row.col.f32.tf32.tf32.f32 "
        "{%0,%1,%2,%3}, {%4,%5,%6,%7}, {%8,%9}, {%0,%1,%2,%3};"
        : "+f"(c[0]), "+f"(c[1]), "+f"(c[2]), "+f"(c[3])
        : "r"(a[0]), "r"(a[1]), "r"(a[2]), "r"(a[3]), "r"(b[0]), "r"(b[1]));
}
__device__ __forceinline__ void cp16(uint32_t dst, const void* src) {
    asm volatile("cp.async.cg.shared.global [%0], [%1], 16;" :: "r"(dst), "l"(src));
}
#define CP_COMMIT() asm volatile("cp.async.commit_group;" ::: "memory")
#define CP_WAIT0()  asm volatile("cp.async.wait_group 0;" ::: "memory")

// ---------------------------------------------------------------------------
// prep W (fused): g_W2[b][tap][co][ci] = tf32(eps[b][co][ci*9+tap]*exp(psi)+mu)
// grid (CO_, BB), block 128 (thread = ci)
// ---------------------------------------------------------------------------
__global__ void prepw_kernel(const float* __restrict__ eps,
                             const float* __restrict__ psi,
                             const float* __restrict__ mu) {
    int ci = threadIdx.x;
    int co = blockIdx.x, b = blockIdx.y;
    const float* e = eps + ((size_t)(b * CO_ + co) * CI_ + ci) * 9;
    const float* p = psi + ((size_t)co * CI_ + ci) * 9;
    const float* m = mu  + ((size_t)co * CI_ + ci) * 9;
    float v[9];
#pragma unroll
    for (int k = 0; k < 9; k++)
        v[k] = fmaf(e[k], __expf(p[k]), m[k]);
#pragma unroll
    for (int k = 0; k < 9; k++)
        g_W2[((size_t)(b * 9 + k) * CO_ + co) * CI_ + ci] = __uint_as_float(f32_to_tf32(v[k]));
}

// ---------------------------------------------------------------------------
// zero pad border of g_pad
// ---------------------------------------------------------------------------
__global__ void zeroborder_kernel() {
    int gi = blockIdx.x * 256 + threadIdx.x;
    if (gi >= BB * 228 * 32) return;
    int b = gi / (228 * 32);
    int r = gi % (228 * 32);
    int pi = r >> 5, f = r & 31;
    int y, x;
    if (pi < 58)       { y = 0;            x = pi; }
    else if (pi < 116) { y = 57;           x = pi - 58; }
    else if (pi < 172) { y = pi - 116 + 1; x = 0; }
    else               { y = pi - 172 + 1; x = 57; }
    ((float4*)g_pad)[(((size_t)b * PADW + y) * PADW + x) * 32 + f] = make_float4(0.f, 0.f, 0.f, 0.f);
}

// ---------------------------------------------------------------------------
// NCHW -> padded NHWC, pre-rounded to tf32
// grid (98, 4, 32), block (32, 8)
// ---------------------------------------------------------------------------
__global__ void intrans_kernel(const float* __restrict__ in) {
    __shared__ float t[32][33];
    int b = blockIdx.z, hw0 = blockIdx.x * 32, ci0 = blockIdx.y * 32;
    int tx = threadIdx.x, ty = threadIdx.y;
    const float* ib = in + (size_t)b * CI_ * HW;
#pragma unroll
    for (int j = 0; j < 32; j += 8)
        t[ty + j][tx] = ib[(size_t)(ci0 + ty + j) * HW + hw0 + tx];
    __syncthreads();
#pragma unroll
    for (int j = 0; j < 32; j += 8) {
        int hw = hw0 + ty + j;
        int y = hw / WW, x = hw - y * WW;
        g_pad[(((size_t)b * PADW + y + 1) * PADW + (x + 1)) * CI_ + ci0 + tx] =
            __uint_as_float(f32_to_tf32(t[tx][ty + j]));
    }
}

// ---------------------------------------------------------------------------
// conv: implicit GEMM, mma.sync tf32, cp.async staging.
// CTA = 112 pixels (2 rows) x 128 co. Outer loop: 4 ci-chunks of 32.
// A staged once per chunk covering the full 4-row x 58-col halo (232 rows) ->
// all 9 taps read the same smem at offset u*58+v. B double-buffered per tap.
// grid (28, 32), block 256.
// ---------------------------------------------------------------------------
__global__ __launch_bounds__(256, 2) void conv_mma(float* __restrict__ out) {
    extern __shared__ __align__(128) char smem[];
    uint32_t As_u = smem_to_u32(smem);
    uint32_t Bs_u = As_u + ABYTES;

    int tid = threadIdx.x, lid = tid & 31, wid = tid >> 5;
    int tile = blockIdx.x, b = blockIdx.y;
    int y0 = tile * 2;

    // A source: padded rows y0..y0+3, all 58 cols, row-linear (q = yr*58+xx)
    const float* apage = g_pad + (((size_t)b * PADW + y0) * PADW) * CI_;
    const float* wpage = g_W2 + (size_t)b * 9 * CO_ * CI_;

    // ---- fragment lane addressing ----
    int rA    = lid & 7;
    int add8A = ((lid >> 3) & 1) << 3;
    int jAh   = lid >> 4;               // A k-block half
    int jBh   = (lid >> 3) & 1;         // B k-block half
    int rowB  = wid * 16 + (((lid >> 4) & 1) << 3) + rA;
    uint32_t b_base  = Bs_u + (uint32_t)rowB * 128;
    uint32_t xorB_sh = (uint32_t)rA << 4;

    // per-lane pixel->row base for each m-fragment (u=0,v=0)
    int row_pq[7];
#pragma unroll
    for (int mf = 0; mf < 7; mf++) {
        int p  = mf * 16 + rA + add8A;
        int py = (p >= 56) ? 1 : 0;
        row_pq[mf] = py * 58 + (p - 56 * py);
    }

    float acc[7][2][4];
#pragma unroll
    for (int mf = 0; mf < 7; mf++)
#pragma unroll
        for (int nf = 0; nf < 2; nf++)
#pragma unroll
            for (int q = 0; q < 4; q++) acc[mf][nf][q] = 0.f;

    int buf = 0;
    for (int cc = 0; cc < 4; cc++) {
        int ccol = cc * 32;
        __syncthreads();   // all reads of As / B buffers from previous cc done

        // ---- stage A: 1856 x 16B, swizzled ----
#pragma unroll
        for (int t = 0; t < 8; t++) {
            int c = tid + t * 256;
            if (t < 7 || c < AROWS * 8) {
                int q = c >> 3, j = c & 7;
                cp16(As_u + (uint32_t)(q * 128 + ((j ^ (q & 7)) << 4)),
                     apage + (size_t)q * CI_ + ccol + j * 4);
            }
        }
        // ---- stage B tap 0 into buf ----
        {
            const float* wsrc = wpage + ccol;
#pragma unroll
            for (int t = 0; t < 4; t++) {
                int c = tid + t * 256;
                int co = c >> 3, j = c & 7;
                cp16(Bs_u + (uint32_t)(buf * BBYTES + co * 128 + ((j ^ (co & 7)) << 4)),
                     wsrc + (size_t)co * CI_ + j * 4);
            }
        }
        CP_COMMIT();

        for (int uv = 0; uv < 9; uv++) {
            CP_WAIT0();
            __syncthreads();

            if (uv < 8) {   // prefetch next tap's B into other buffer
                const float* wsrc = wpage + (size_t)(uv + 1) * CO_ * CI_ + ccol;
#pragma unroll
                for (int t = 0; t < 4; t++) {
                    int c = tid + t * 256;
                    int co = c >> 3, j = c & 7;
                    cp16(Bs_u + (uint32_t)((buf ^ 1) * BBYTES + co * 128 + ((j ^ (co & 7)) << 4)),
                         wsrc + (size_t)co * CI_ + j * 4);
                }
                CP_COMMIT();
            }

            // ---- compute tap uv from As (row shift u*58+v) and Bs[buf] ----
            int u = uv / 3, v = uv - u * 3;
            int du = u * 58 + v;
            uint32_t abase[7], axsh[7];
#pragma unroll
            for (int mf = 0; mf < 7; mf++) {
                int q = row_pq[mf] + du;
                abase[mf] = As_u + (uint32_t)q * 128;
                axsh[mf]  = (uint32_t)(q & 7) << 4;
            }
            uint32_t bbuf_base = b_base + (uint32_t)buf * BBYTES;
#pragma unroll
            for (int kk = 0; kk < 4; kk++) {
                uint32_t bf[4];
                ldsm_x4(bf, bbuf_base + ((((uint32_t)(kk * 2 + jBh)) << 4) ^ xorB_sh));
#pragma unroll
                for (int mf = 0; mf < 7; mf++) {
                    uint32_t af[4];
                    ldsm_x4(af, abase[mf] + ((((uint32_t)(kk * 2 + jAh)) << 4) ^ axsh[mf]));
                    mma_tf32(acc[mf][0], af, bf);
                    mma_tf32(acc[mf][1], af, bf + 2);
                }
            }
            buf ^= 1;
        }
    }

    // ---- epilogue: direct NCHW stores (64B-contiguous per tg group) ----
    float* ob = out + (size_t)b * CO_ * HW;
    int g = lid >> 2, tg = lid & 3;
#pragma unroll
    for (int mf = 0; mf < 7; mf++) {
#pragma unroll
        for (int h = 0; h < 2; h++) {
            int row = mf * 16 + g + 8 * h;
            int r1 = (row >= 56) ? 1 : 0;
            size_t pix = (size_t)(y0 + r1) * WW + (row - 56 * r1);
#pragma unroll
            for (int nf = 0; nf < 2; nf++) {
                int col = wid * 16 + nf * 8 + (tg << 1);
                ob[(size_t)col * HW + pix]       = acc[mf][nf][2 * h];
                ob[(size_t)(col + 1) * HW + pix] = acc[mf][nf][2 * h + 1];
            }
        }
    }
}

// ---------------------------------------------------------------------------
extern "C" void kernel_launch(void* const* d_in, const int* in_sizes, int n_in,
                              void* d_out, int out_size) {
    const float* input = (const float*)d_in[0];   // [32,128,56,56]
    const float* eps   = (const float*)d_in[1];   // [32,128,128,3,3]
    const float* psi   = (const float*)d_in[2];   // [128,128,3,3]
    const float* mu    = (const float*)d_in[3];   // [128,128,3,3]
    float* out = (float*)d_out;                   // [32,128,56,56]

    prepw_kernel<<<dim3(CO_, BB), 128>>>(eps, psi, mu);
    zeroborder_kernel<<<912, 256>>>();
    intrans_kernel<<<dim3(98, 4, BB), dim3(32, 8)>>>(input);

    cudaFuncSetAttribute(conv_mma, cudaFuncAttributeMaxDynamicSharedMemorySize, SMEM_CONV);
    conv_mma<<<dim3(28, BB), 256, SMEM_CONV>>>(out);
}